// round 10
// baseline (speedup 1.0000x reference)
#include <cuda_runtime.h>
#include <math.h>

#define T_STEPS 4096
#define H_DIM   2048
#define O_DIM   512

#define RNN_CTAS    128
#define RNN_THREADS 256

#define SENTINEL 0x7f800001u   // NaN payload; tanh(finite) can never produce it

// ---------------- device scratch (allocation-free rule) ----------------
__device__ float g_xp[(size_t)T_STEPS * H_DIM];   // x @ W_ih^T + b_ih + b_hh
__device__ float g_hs[(size_t)T_STEPS * H_DIM];   // all hidden states h_t

// Morally-strong volatile ops for the data-as-flag protocol (R8, proven).
__device__ __forceinline__ uint4 ld_vol_u4(const uint4* p)
{
    uint4 v;
    asm volatile("ld.volatile.global.v4.u32 {%0,%1,%2,%3}, [%4];"
                 : "=r"(v.x), "=r"(v.y), "=r"(v.z), "=r"(v.w)
                 : "l"(p) : "memory");
    return v;
}
__device__ __forceinline__ void st_vol_f32(float* p, float v)
{
    asm volatile("st.volatile.global.f32 [%0], %1;"
                 :: "l"(p), "f"(v) : "memory");
}
__device__ __forceinline__ bool has_sent(uint4 v)
{
    return (v.x == SENTINEL) | (v.y == SENTINEL) |
           (v.z == SENTINEL) | (v.w == SENTINEL);
}

// packed f32x2 helpers
__device__ __forceinline__ void fma2(unsigned long long& acc,
                                     unsigned long long a, unsigned long long b)
{
    asm("fma.rn.f32x2 %0, %1, %2, %0;" : "+l"(acc) : "l"(a), "l"(b));
}
__device__ __forceinline__ unsigned long long pack2u(unsigned lo, unsigned hi)
{
    unsigned long long v;
    asm("mov.b64 %0, {%1, %2};" : "=l"(v) : "r"(lo), "r"(hi));
    return v;
}
__device__ __forceinline__ float2 unpack2(unsigned long long v)
{
    float2 r;
    asm("mov.b64 {%0, %1}, %2;" : "=f"(r.x), "=f"(r.y) : "l"(v));
    return r;
}

// ---------------- sentinel reset (graph-replay safe) -------------------
__global__ void reset_hs_kernel()
{
    size_t i = (size_t)blockIdx.x * blockDim.x + threadIdx.x;
    ((uint4*)g_hs)[i] = make_uint4(SENTINEL, SENTINEL, SENTINEL, SENTINEL);
}

// ---------------- persistent recurrence kernel -------------------------
// h_t = tanh(xp_t + W_hh @ h_{t-1}); k-split layout:
// 128 CTAs x 16 rows; warp w owns k-slice [w*256, w*256+256) for ALL 16 rows.
// Thread (w,l) polls its TWO 16B chunks (k = w*256 + {0,128} + l*4) DIRECTLY
// into registers — the polled words ARE the FMA operands, so there is no SMEM
// h staging and no staging barrier. Both chunks are polled concurrently
// (one L2 RTT, not two serial ones — this was R8/R9's hidden serial cost).
// Cross-warp combine via double-buffered smem partials -> ONE bar per step.
// Sync: R8's proven data-as-flag volatile protocol.
__global__ void __launch_bounds__(RNN_THREADS, 1)
rnn_kernel(const float* __restrict__ W_hh, const float* __restrict__ h0)
{
    __shared__ __align__(16) float pbuf[2][16][RNN_THREADS]; // partials, dbl-buffered
    const int tid  = threadIdx.x;
    const int lane = tid & 31;
    const int wid  = tid >> 5;                    // 0..7
    const int rowbase = blockIdx.x * 16;

    // Weights: wp[r][p] = 4 floats (2 f32x2) at k = wid*256 + p*128 + lane*4.
    ulonglong2 wp[16][2];   // 128 regs
#pragma unroll
    for (int r = 0; r < 16; r++) {
#pragma unroll
        for (int p = 0; p < 2; p++) {
            const ulonglong2* src = (const ulonglong2*)
                (W_hh + (size_t)(rowbase + r) * H_DIM + wid * 256 + p * 128 + lane * 4);
            wp[r][p] = __ldg(src);
        }
    }

    const int ci0 = wid * 64 + lane;        // uint4 index of chunk p=0
    const int ci1 = wid * 64 + 32 + lane;   // uint4 index of chunk p=1

    for (int t = 0; t < T_STEPS; t++) {
        const int buf = t & 1;

        // xp prefetch: warp w outputs rows 2w, 2w+1.
        float xpv0 = 0.f, xpv1 = 0.f;
        if (lane == 0) {
            xpv0 = __ldg(&g_xp[(size_t)t * H_DIM + rowbase + 2 * wid]);
            xpv1 = __ldg(&g_xp[(size_t)t * H_DIM + rowbase + 2 * wid + 1]);
        }

        // Acquire this thread's h-slice directly into registers.
        // Both chunks polled CONCURRENTLY: both loads issue each iteration
        // until each is sentinel-free (one RTT when data is ready).
        uint4 ua, ub;
        if (t == 0) {
            ua = __ldg(&((const uint4*)h0)[ci0]);
            ub = __ldg(&((const uint4*)h0)[ci1]);
        } else {
            const uint4* hp = (const uint4*)(g_hs + (size_t)(t - 1) * H_DIM);
            bool da = false, db = false;
            do {
                if (!da) { ua = ld_vol_u4(hp + ci0); da = !has_sent(ua); }
                if (!db) { ub = ld_vol_u4(hp + ci1); db = !has_sent(ub); }
            } while (!(da && db));
        }
        unsigned long long a0 = pack2u(ua.x, ua.y);
        unsigned long long a1 = pack2u(ua.z, ua.w);
        unsigned long long b0 = pack2u(ub.x, ub.y);
        unsigned long long b1 = pack2u(ub.z, ub.w);

        // Partials: 16 rows x 8 k-elems per lane, f32x2 packed.
        // Same accumulation order as the passing R9 kernel.
        unsigned long long acc2[16];
#pragma unroll
        for (int r = 0; r < 16; r++) {
            acc2[r] = 0ull;
            fma2(acc2[r], wp[r][0].x, a0);
            fma2(acc2[r], wp[r][0].y, a1);
            fma2(acc2[r], wp[r][1].x, b0);
            fma2(acc2[r], wp[r][1].y, b1);
        }

        // Horizontal add + write partials (16 STS.32, conflict-free: col=tid).
#pragma unroll
        for (int r = 0; r < 16; r++) {
            float2 pr = unpack2(acc2[r]);
            pbuf[buf][r][tid] = pr.x + pr.y;
        }
        __syncthreads();   // partials visible; also WAR-guards pbuf[buf] reuse

        // Final reduce: warp w reduces rows 2w and 2w+1 over 256 partials.
        float s0 = 0.f, s1 = 0.f;
#pragma unroll
        for (int k = 0; k < 8; k++) {
            s0 += pbuf[buf][2 * wid][lane + 32 * k];
            s1 += pbuf[buf][2 * wid + 1][lane + 32 * k];
        }
#pragma unroll
        for (int off = 16; off > 0; off >>= 1) {
            s0 += __shfl_down_sync(0xffffffffu, s0, off);
            s1 += __shfl_down_sync(0xffffffffu, s1, off);
        }

        // Publish h_t: volatile word stores, self-announcing (R8 protocol).
        if (lane == 0) {
            st_vol_f32(&g_hs[(size_t)t * H_DIM + rowbase + 2 * wid],     tanhf(xpv0 + s0));
            st_vol_f32(&g_hs[(size_t)t * H_DIM + rowbase + 2 * wid + 1], tanhf(xpv1 + s1));
        }
    }
}

// ---------------- tiled fp32 NT GEMM: C[M,N] = A[M,K] @ B[N,K]^T + bias --
// (R8's scalar version, unchanged — known good.)
// PHASE 0: A = param (x),   C = g_xp,  bias = b_ih + b_hh
// PHASE 1: A = g_hs,        C = param, bias = b_lin
#define BM 128
#define BN 64
#define BK 16

template<int PHASE>
__global__ void __launch_bounds__(256, 2)
gemm_nt_bias(const float* __restrict__ A_param,
             const float* __restrict__ B,
             const float* __restrict__ bias1,
             const float* __restrict__ bias2,
             float* __restrict__ C_param,
             int M, int N, int K)
{
    __shared__ __align__(16) float As[BK][BM + 4];
    __shared__ __align__(16) float Bs[BK][BN + 4];

    const float* A = (PHASE == 0) ? A_param : g_hs;
    float*       C = (PHASE == 0) ? g_xp    : C_param;

    const int tid = threadIdx.x;
    const int m0  = blockIdx.y * BM;
    const int n0  = blockIdx.x * BN;
    const int ty  = tid >> 4;    // 0..15 -> rows ty*8..+7
    const int tx  = tid & 15;    // 0..15 -> cols tx*4..+3

    float acc[8][4];
#pragma unroll
    for (int i = 0; i < 8; i++)
#pragma unroll
        for (int j = 0; j < 4; j++) acc[i][j] = 0.f;

    for (int k0 = 0; k0 < K; k0 += BK) {
        // A tile: 128x16 = 512 float4, 2 per thread
#pragma unroll
        for (int it = 0; it < 2; it++) {
            int idx = tid + it * 256;
            int row = idx >> 2, kq = idx & 3;
            float4 v = *(const float4*)(A + (size_t)(m0 + row) * K + k0 + kq * 4);
            As[kq * 4 + 0][row] = v.x;
            As[kq * 4 + 1][row] = v.y;
            As[kq * 4 + 2][row] = v.z;
            As[kq * 4 + 3][row] = v.w;
        }
        // B tile: 64x16 = 256 float4, 1 per thread
        {
            int row = tid >> 2, kq = tid & 3;
            float4 v = *(const float4*)(B + (size_t)(n0 + row) * K + k0 + kq * 4);
            Bs[kq * 4 + 0][row] = v.x;
            Bs[kq * 4 + 1][row] = v.y;
            Bs[kq * 4 + 2][row] = v.z;
            Bs[kq * 4 + 3][row] = v.w;
        }
        __syncthreads();

#pragma unroll
        for (int kk = 0; kk < BK; kk++) {
            float4 a0 = *(const float4*)&As[kk][ty * 8];
            float4 a1 = *(const float4*)&As[kk][ty * 8 + 4];
            float4 bv = *(const float4*)&Bs[kk][tx * 4];
            float av[8] = {a0.x, a0.y, a0.z, a0.w, a1.x, a1.y, a1.z, a1.w};
            float bb[4] = {bv.x, bv.y, bv.z, bv.w};
#pragma unroll
            for (int i = 0; i < 8; i++)
#pragma unroll
                for (int j = 0; j < 4; j++)
                    acc[i][j] += av[i] * bb[j];
        }
        __syncthreads();
    }

    // epilogue: bias + store
    float bsum[4];
#pragma unroll
    for (int j = 0; j < 4; j++) {
        int n = n0 + tx * 4 + j;
        float bv = __ldg(&bias1[n]);
        if (bias2) bv += __ldg(&bias2[n]);
        bsum[j] = bv;
    }
#pragma unroll
    for (int i = 0; i < 8; i++) {
        float4 o;
        o.x = acc[i][0] + bsum[0];
        o.y = acc[i][1] + bsum[1];
        o.z = acc[i][2] + bsum[2];
        o.w = acc[i][3] + bsum[3];
        *(float4*)(C + (size_t)(m0 + ty * 8 + i) * N + n0 + tx * 4) = o;
    }
}

// ---------------- launch ------------------------------------------------
extern "C" void kernel_launch(void* const* d_in, const int* in_sizes, int n_in,
                              void* d_out, int out_size)
{
    const float* x     = (const float*)d_in[0];  // (T,1,H)
    const float* W_ih  = (const float*)d_in[1];  // (H,H)
    const float* W_hh  = (const float*)d_in[2];  // (H,H)
    const float* b_ih  = (const float*)d_in[3];  // (H)
    const float* b_hh  = (const float*)d_in[4];  // (H)
    const float* W_lin = (const float*)d_in[5];  // (O,H)
    const float* b_lin = (const float*)d_in[6];  // (O)
    const float* h0    = (const float*)d_in[7];  // (1,1,H)
    float* out = (float*)d_out;                  // (T,1,O)

    // Reset g_hs to sentinel (must precede rnn_kernel every launch/replay).
    reset_hs_kernel<<<(T_STEPS * H_DIM / 4) / 256, 256>>>();

    // Phase 1: g_xp = x @ W_ih^T + b_ih + b_hh
    gemm_nt_bias<0><<<dim3(H_DIM / BN, T_STEPS / BM), 256>>>(
        x, W_ih, b_ih, b_hh, nullptr, T_STEPS, H_DIM, H_DIM);

    // Phase 2: sequential recurrence -> g_hs
    rnn_kernel<<<RNN_CTAS, RNN_THREADS>>>(W_hh, h0);

    // Phase 3: out = g_hs @ W_lin^T + b_lin
    gemm_nt_bias<1><<<dim3(O_DIM / BN, T_STEPS / BM), 256>>>(
        nullptr, W_lin, b_lin, nullptr, out, T_STEPS, O_DIM, H_DIM);
}

// round 11
// speedup vs baseline: 1.6579x; 1.6579x over previous
#include <cuda_runtime.h>
#include <math.h>

#define T_STEPS 4096
#define H_DIM   2048
#define O_DIM   512

#define RNN_CTAS    128
#define RNN_THREADS 256

#define SENTINEL 0x7f800001u   // NaN payload; tanh(finite) can never produce it

// ---------------- device scratch (allocation-free rule) ----------------
__device__ float g_xp[(size_t)T_STEPS * H_DIM];   // x @ W_ih^T + b_ih + b_hh
__device__ float g_hs[(size_t)T_STEPS * H_DIM];   // all hidden states h_t

// Morally-strong volatile ops for the data-as-flag protocol (R8, proven).
__device__ __forceinline__ uint4 ld_vol_u4(const uint4* p)
{
    uint4 v;
    asm volatile("ld.volatile.global.v4.u32 {%0,%1,%2,%3}, [%4];"
                 : "=r"(v.x), "=r"(v.y), "=r"(v.z), "=r"(v.w)
                 : "l"(p) : "memory");
    return v;
}
__device__ __forceinline__ void st_vol_f32(float* p, float v)
{
    asm volatile("st.volatile.global.f32 [%0], %1;"
                 :: "l"(p), "f"(v) : "memory");
}
__device__ __forceinline__ bool has_sent(uint4 v)
{
    return (v.x == SENTINEL) | (v.y == SENTINEL) |
           (v.z == SENTINEL) | (v.w == SENTINEL);
}

// ---------------- sentinel reset (graph-replay safe) -------------------
// 8M floats = 2M uint4; grid 8192 x 256.
__global__ void reset_hs_kernel()
{
    size_t i = (size_t)blockIdx.x * blockDim.x + threadIdx.x;
    ((uint4*)g_hs)[i] = make_uint4(SENTINEL, SENTINEL, SENTINEL, SENTINEL);
}

// ---------------- persistent recurrence kernel -------------------------
// EXACTLY the R8 passing kernel (best: 6530us) with ONE change: the two
// 16B h-chunks are polled CONCURRENTLY in a single loop instead of
// serially (R8 completed chunk a's poll before starting chunk b's,
// adding one dependent L2 round-trip per step).
// 128 CTAs x 16 rows. 8 warps/CTA, 2 rows/warp, 64 k-elems (16 float4)/lane.
// Sync: data-as-flag, volatile (morally strong) ld/st. No fences, no flags.
__global__ void __launch_bounds__(RNN_THREADS, 1)
rnn_kernel(const float* __restrict__ W_hh, const float* __restrict__ h0)
{
    __shared__ __align__(16) float hbuf[H_DIM];
    const int tid  = threadIdx.x;
    const int lane = tid & 31;
    const int wid  = tid >> 5;                    // 0..7
    const int r0   = blockIdx.x * 16 + wid * 2;   // this warp's two rows

    // Load this warp's two weight rows into registers.
    float4 w0[16], w1[16];
    const float4* W0 = (const float4*)(W_hh + (size_t)r0 * H_DIM);
    const float4* W1 = (const float4*)(W_hh + (size_t)(r0 + 1) * H_DIM);
#pragma unroll
    for (int j = 0; j < 16; j++) {
        w0[j] = __ldg(&W0[j * 32 + lane]);
        w1[j] = __ldg(&W1[j * 32 + lane]);
    }

    for (int t = 0; t < T_STEPS; t++) {
        // xp prefetch: independent of h_{t-1}
        float xpv0 = 0.f, xpv1 = 0.f;
        if (lane == 0) {
            xpv0 = __ldg(&g_xp[(size_t)t * H_DIM + r0]);
            xpv1 = __ldg(&g_xp[(size_t)t * H_DIM + r0 + 1]);
        }

        // Acquire h_{t-1}: both chunks polled CONCURRENTLY (one RTT when
        // ready, not two serial ones). The poll IS the staging load.
        float4 a4, b4;
        if (t == 0) {
            a4 = __ldg(&((const float4*)h0)[tid]);
            b4 = __ldg(&((const float4*)h0)[tid + RNN_THREADS]);
        } else {
            const uint4* hp = (const uint4*)(g_hs + (size_t)(t - 1) * H_DIM);
            uint4 ua, ub;
            bool da = false, db = false;
            do {
                if (!da) { ua = ld_vol_u4(hp + tid);               da = !has_sent(ua); }
                if (!db) { ub = ld_vol_u4(hp + tid + RNN_THREADS); db = !has_sent(ub); }
            } while (!(da && db));
            a4 = make_float4(__uint_as_float(ua.x), __uint_as_float(ua.y),
                             __uint_as_float(ua.z), __uint_as_float(ua.w));
            b4 = make_float4(__uint_as_float(ub.x), __uint_as_float(ub.y),
                             __uint_as_float(ub.z), __uint_as_float(ub.w));
        }

        __syncthreads();   // previous iteration's LDS reads of hbuf are done
        ((float4*)hbuf)[tid]               = a4;
        ((float4*)hbuf)[tid + RNN_THREADS] = b4;
        __syncthreads();   // staging visible

        float acc0 = 0.f, acc1 = 0.f;
#pragma unroll
        for (int j = 0; j < 16; j++) {
            float4 h4 = ((const float4*)hbuf)[j * 32 + lane];  // conflict-free
            acc0 += w0[j].x * h4.x; acc1 += w1[j].x * h4.x;
            acc0 += w0[j].y * h4.y; acc1 += w1[j].y * h4.y;
            acc0 += w0[j].z * h4.z; acc1 += w1[j].z * h4.z;
            acc0 += w0[j].w * h4.w; acc1 += w1[j].w * h4.w;
        }

#pragma unroll
        for (int off = 16; off > 0; off >>= 1) {
            acc0 += __shfl_down_sync(0xffffffffu, acc0, off);
            acc1 += __shfl_down_sync(0xffffffffu, acc1, off);
        }

        // Publish h_t: volatile word stores, self-announcing.
        if (lane == 0) {
            st_vol_f32(&g_hs[(size_t)t * H_DIM + r0],     tanhf(xpv0 + acc0));
            st_vol_f32(&g_hs[(size_t)t * H_DIM + r0 + 1], tanhf(xpv1 + acc1));
        }
    }
}

// ---------------- tiled fp32 NT GEMM: C[M,N] = A[M,K] @ B[N,K]^T + bias --
// (R8's scalar version, unchanged — known good.)
// PHASE 0: A = param (x),   C = g_xp,  bias = b_ih + b_hh
// PHASE 1: A = g_hs,        C = param, bias = b_lin
#define BM 128
#define BN 64
#define BK 16

template<int PHASE>
__global__ void __launch_bounds__(256, 2)
gemm_nt_bias(const float* __restrict__ A_param,
             const float* __restrict__ B,
             const float* __restrict__ bias1,
             const float* __restrict__ bias2,
             float* __restrict__ C_param,
             int M, int N, int K)
{
    __shared__ __align__(16) float As[BK][BM + 4];
    __shared__ __align__(16) float Bs[BK][BN + 4];

    const float* A = (PHASE == 0) ? A_param : g_hs;
    float*       C = (PHASE == 0) ? g_xp    : C_param;

    const int tid = threadIdx.x;
    const int m0  = blockIdx.y * BM;
    const int n0  = blockIdx.x * BN;
    const int ty  = tid >> 4;    // 0..15 -> rows ty*8..+7
    const int tx  = tid & 15;    // 0..15 -> cols tx*4..+3

    float acc[8][4];
#pragma unroll
    for (int i = 0; i < 8; i++)
#pragma unroll
        for (int j = 0; j < 4; j++) acc[i][j] = 0.f;

    for (int k0 = 0; k0 < K; k0 += BK) {
        // A tile: 128x16 = 512 float4, 2 per thread
#pragma unroll
        for (int it = 0; it < 2; it++) {
            int idx = tid + it * 256;
            int row = idx >> 2, kq = idx & 3;
            float4 v = *(const float4*)(A + (size_t)(m0 + row) * K + k0 + kq * 4);
            As[kq * 4 + 0][row] = v.x;
            As[kq * 4 + 1][row] = v.y;
            As[kq * 4 + 2][row] = v.z;
            As[kq * 4 + 3][row] = v.w;
        }
        // B tile: 64x16 = 256 float4, 1 per thread
        {
            int row = tid >> 2, kq = tid & 3;
            float4 v = *(const float4*)(B + (size_t)(n0 + row) * K + k0 + kq * 4);
            Bs[kq * 4 + 0][row] = v.x;
            Bs[kq * 4 + 1][row] = v.y;
            Bs[kq * 4 + 2][row] = v.z;
            Bs[kq * 4 + 3][row] = v.w;
        }
        __syncthreads();

#pragma unroll
        for (int kk = 0; kk < BK; kk++) {
            float4 a0 = *(const float4*)&As[kk][ty * 8];
            float4 a1 = *(const float4*)&As[kk][ty * 8 + 4];
            float4 bv = *(const float4*)&Bs[kk][tx * 4];
            float av[8] = {a0.x, a0.y, a0.z, a0.w, a1.x, a1.y, a1.z, a1.w};
            float bb[4] = {bv.x, bv.y, bv.z, bv.w};
#pragma unroll
            for (int i = 0; i < 8; i++)
#pragma unroll
                for (int j = 0; j < 4; j++)
                    acc[i][j] += av[i] * bb[j];
        }
        __syncthreads();
    }

    // epilogue: bias + store
    float bsum[4];
#pragma unroll
    for (int j = 0; j < 4; j++) {
        int n = n0 + tx * 4 + j;
        float bv = __ldg(&bias1[n]);
        if (bias2) bv += __ldg(&bias2[n]);
        bsum[j] = bv;
    }
#pragma unroll
    for (int i = 0; i < 8; i++) {
        float4 o;
        o.x = acc[i][0] + bsum[0];
        o.y = acc[i][1] + bsum[1];
        o.z = acc[i][2] + bsum[2];
        o.w = acc[i][3] + bsum[3];
        *(float4*)(C + (size_t)(m0 + ty * 8 + i) * N + n0 + tx * 4) = o;
    }
}

// ---------------- launch ------------------------------------------------
extern "C" void kernel_launch(void* const* d_in, const int* in_sizes, int n_in,
                              void* d_out, int out_size)
{
    const float* x     = (const float*)d_in[0];  // (T,1,H)
    const float* W_ih  = (const float*)d_in[1];  // (H,H)
    const float* W_hh  = (const float*)d_in[2];  // (H,H)
    const float* b_ih  = (const float*)d_in[3];  // (H)
    const float* b_hh  = (const float*)d_in[4];  // (H)
    const float* W_lin = (const float*)d_in[5];  // (O,H)
    const float* b_lin = (const float*)d_in[6];  // (O)
    const float* h0    = (const float*)d_in[7];  // (1,1,H)
    float* out = (float*)d_out;                  // (T,1,O)

    // Reset g_hs to sentinel (must precede rnn_kernel every launch/replay).
    reset_hs_kernel<<<(T_STEPS * H_DIM / 4) / 256, 256>>>();

    // Phase 1: g_xp = x @ W_ih^T + b_ih + b_hh
    gemm_nt_bias<0><<<dim3(H_DIM / BN, T_STEPS / BM), 256>>>(
        x, W_ih, b_ih, b_hh, nullptr, T_STEPS, H_DIM, H_DIM);

    // Phase 2: sequential recurrence -> g_hs
    rnn_kernel<<<RNN_CTAS, RNN_THREADS>>>(W_hh, h0);

    // Phase 3: out = g_hs @ W_lin^T + b_lin
    gemm_nt_bias<1><<<dim3(O_DIM / BN, T_STEPS / BM), 256>>>(
        nullptr, W_lin, b_lin, nullptr, out, T_STEPS, O_DIM, H_DIM);
}

// round 14
// speedup vs baseline: 1.7711x; 1.0682x over previous
#include <cuda_runtime.h>
#include <math.h>

#define T_STEPS 4096
#define H_DIM   2048
#define O_DIM   512

#define RNN_CTAS    128
#define RNN_THREADS 256

#define SENTINEL 0x7f800001u   // NaN payload; tanh(finite) can never produce it

// ---------------- device scratch (allocation-free rule) ----------------
__device__ float g_xp[(size_t)T_STEPS * H_DIM];   // x @ W_ih^T + b_ih + b_hh
__device__ float g_hs[(size_t)T_STEPS * H_DIM];   // all hidden states h_t

// Morally-strong volatile ops for the data-as-flag protocol (R8, proven).
__device__ __forceinline__ uint4 ld_vol_u4(const uint4* p)
{
    uint4 v;
    asm volatile("ld.volatile.global.v4.u32 {%0,%1,%2,%3}, [%4];"
                 : "=r"(v.x), "=r"(v.y), "=r"(v.z), "=r"(v.w)
                 : "l"(p) : "memory");
    return v;
}
__device__ __forceinline__ void st_vol_f32(float* p, float v)
{
    asm volatile("st.volatile.global.f32 [%0], %1;"
                 :: "l"(p), "f"(v) : "memory");
}
__device__ __forceinline__ bool has_sent(uint4 v)
{
    return (v.x == SENTINEL) | (v.y == SENTINEL) |
           (v.z == SENTINEL) | (v.w == SENTINEL);
}

// ---------------- sentinel reset (graph-replay safe) -------------------
// 8M floats = 2M uint4; grid 8192 x 256.
__global__ void reset_hs_kernel()
{
    size_t i = (size_t)blockIdx.x * blockDim.x + threadIdx.x;
    ((uint4*)g_hs)[i] = make_uint4(SENTINEL, SENTINEL, SENTINEL, SENTINEL);
}

// ---------------- persistent recurrence kernel -------------------------
// R11 base (best passing) with three serial-tail cuts:
//  (1) JOINT butterfly reduction: acc0/acc1 folded by lane parity, then 4
//      bfly levels -> 5 total SHFL levels instead of 10; even lanes end
//      with s0, odd lanes with s1.
//  (2) lanes 0 and 1 publish rows r0, r0+1 IN PARALLEL.
//  (3) double-buffered hbuf -> ONE __syncthreads per step.
// 128 CTAs x 16 rows. 8 warps/CTA, 2 rows/warp, 64 k-elems (16 float4)/lane.
// Sync: data-as-flag, volatile (morally strong) ld/st. No fences, no flags.
__global__ void __launch_bounds__(RNN_THREADS, 1)
rnn_kernel(const float* __restrict__ W_hh, const float* __restrict__ h0)
{
    __shared__ __align__(16) float hbuf[2][H_DIM];   // double-buffered h
    const int tid  = threadIdx.x;
    const int lane = tid & 31;
    const int wid  = tid >> 5;                    // 0..7
    const int r0   = blockIdx.x * 16 + wid * 2;   // this warp's two rows
    const bool odd = lane & 1;

    // Load this warp's two weight rows into registers.
    float4 w0[16], w1[16];
    const float4* W0 = (const float4*)(W_hh + (size_t)r0 * H_DIM);
    const float4* W1 = (const float4*)(W_hh + (size_t)(r0 + 1) * H_DIM);
#pragma unroll
    for (int j = 0; j < 16; j++) {
        w0[j] = __ldg(&W0[j * 32 + lane]);
        w1[j] = __ldg(&W1[j * 32 + lane]);
    }

    for (int t = 0; t < T_STEPS; t++) {
        const int buf = t & 1;

        // xp prefetch: lanes 0,1 each load their own row's xp (they publish
        // rows r0, r0+1 respectively at the end of the step).
        float xpv = 0.f;
        if (lane < 2) {
            xpv = __ldg(&g_xp[(size_t)t * H_DIM + r0 + lane]);
        }

        // Acquire h_{t-1}: both chunks polled concurrently (data-as-flag).
        float4 a4, b4;
        if (t == 0) {
            a4 = __ldg(&((const float4*)h0)[tid]);
            b4 = __ldg(&((const float4*)h0)[tid + RNN_THREADS]);
        } else {
            const uint4* hp = (const uint4*)(g_hs + (size_t)(t - 1) * H_DIM);
            uint4 ua, ub;
            bool da = false, db = false;
            do {
                if (!da) { ua = ld_vol_u4(hp + tid);               da = !has_sent(ua); }
                if (!db) { ub = ld_vol_u4(hp + tid + RNN_THREADS); db = !has_sent(ub); }
            } while (!(da && db));
            a4 = make_float4(__uint_as_float(ua.x), __uint_as_float(ua.y),
                             __uint_as_float(ua.z), __uint_as_float(ua.w));
            b4 = make_float4(__uint_as_float(ub.x), __uint_as_float(ub.y),
                             __uint_as_float(ub.z), __uint_as_float(ub.w));
        }

        // Stage into this step's buffer. WAR on hbuf[buf] (readers at step
        // t-2) is guarded by step t-1's barrier.
        ((float4*)hbuf[buf])[tid]               = a4;
        ((float4*)hbuf[buf])[tid + RNN_THREADS] = b4;
        __syncthreads();   // staging visible (single bar per step)

        float acc0 = 0.f, acc1 = 0.f;
#pragma unroll
        for (int j = 0; j < 16; j++) {
            float4 h4 = ((const float4*)hbuf[buf])[j * 32 + lane];  // conflict-free
            acc0 += w0[j].x * h4.x; acc1 += w1[j].x * h4.x;
            acc0 += w0[j].y * h4.y; acc1 += w1[j].y * h4.y;
            acc0 += w0[j].z * h4.z; acc1 += w1[j].z * h4.z;
            acc0 += w0[j].w * h4.w; acc1 += w1[j].w * h4.w;
        }

        // Joint butterfly reduction (5 levels instead of 10):
        // fold by parity -> even lanes carry row-r0 partials, odd lanes
        // carry row-r0+1 partials; 4 parity-preserving bfly levels finish.
        float mine  = odd ? acc1 : acc0;                 // my parity's row
        float other = odd ? acc0 : acc1;                 // partner row
        mine += __shfl_xor_sync(0xffffffffu, other, 1);  // fold xor-1
#pragma unroll
        for (int off = 2; off < 32; off <<= 1) {
            mine += __shfl_xor_sync(0xffffffffu, mine, off);
        }
        // Now: even lanes all hold s0, odd lanes all hold s1.

        // Publish h_t: lanes 0 and 1 store their rows in parallel.
        if (lane < 2) {
            float v = tanhf(xpv + mine);
            st_vol_f32(&g_hs[(size_t)t * H_DIM + r0 + lane], v);
        }
    }
}

// ---------------- tiled fp32 NT GEMM: C[M,N] = A[M,K] @ B[N,K]^T + bias --
// (R8's scalar version, unchanged — known good, at the fp32 issue floor.)
// PHASE 0: A = param (x),   C = g_xp,  bias = b_ih + b_hh
// PHASE 1: A = g_hs,        C = param, bias = b_lin
#define BM 128
#define BN 64
#define BK 16

template<int PHASE>
__global__ void __launch_bounds__(256, 2)
gemm_nt_bias(const float* __restrict__ A_param,
             const float* __restrict__ B,
             const float* __restrict__ bias1,
             const float* __restrict__ bias2,
             float* __restrict__ C_param,
             int M, int N, int K)
{
    __shared__ __align__(16) float As[BK][BM + 4];
    __shared__ __align__(16) float Bs[BK][BN + 4];

    const float* A = (PHASE == 0) ? A_param : g_hs;
    float*       C = (PHASE == 0) ? g_xp    : C_param;

    const int tid = threadIdx.x;
    const int m0  = blockIdx.y * BM;
    const int n0  = blockIdx.x * BN;
    const int ty  = tid >> 4;    // 0..15 -> rows ty*8..+7
    const int tx  = tid & 15;    // 0..15 -> cols tx*4..+3

    float acc[8][4];
#pragma unroll
    for (int i = 0; i < 8; i++)
#pragma unroll
        for (int j = 0; j < 4; j++) acc[i][j] = 0.f;

    for (int k0 = 0; k0 < K; k0 += BK) {
        // A tile: 128x16 = 512 float4, 2 per thread
#pragma unroll
        for (int it = 0; it < 2; it++) {
            int idx = tid + it * 256;
            int row = idx >> 2, kq = idx & 3;
            float4 v = *(const float4*)(A + (size_t)(m0 + row) * K + k0 + kq * 4);
            As[kq * 4 + 0][row] = v.x;
            As[kq * 4 + 1][row] = v.y;
            As[kq * 4 + 2][row] = v.z;
            As[kq * 4 + 3][row] = v.w;
        }
        // B tile: 64x16 = 256 float4, 1 per thread
        {
            int row = tid >> 2, kq = tid & 3;
            float4 v = *(const float4*)(B + (size_t)(n0 + row) * K + k0 + kq * 4);
            Bs[kq * 4 + 0][row] = v.x;
            Bs[kq * 4 + 1][row] = v.y;
            Bs[kq * 4 + 2][row] = v.z;
            Bs[kq * 4 + 3][row] = v.w;
        }
        __syncthreads();

#pragma unroll
        for (int kk = 0; kk < BK; kk++) {
            float4 a0 = *(const float4*)&As[kk][ty * 8];
            float4 a1 = *(const float4*)&As[kk][ty * 8 + 4];
            float4 bv = *(const float4*)&Bs[kk][tx * 4];
            float av[8] = {a0.x, a0.y, a0.z, a0.w, a1.x, a1.y, a1.z, a1.w};
            float bb[4] = {bv.x, bv.y, bv.z, bv.w};
#pragma unroll
            for (int i = 0; i < 8; i++)
#pragma unroll
                for (int j = 0; j < 4; j++)
                    acc[i][j] += av[i] * bb[j];
        }
        __syncthreads();
    }

    // epilogue: bias + store
    float bsum[4];
#pragma unroll
    for (int j = 0; j < 4; j++) {
        int n = n0 + tx * 4 + j;
        float bv = __ldg(&bias1[n]);
        if (bias2) bv += __ldg(&bias2[n]);
        bsum[j] = bv;
    }
#pragma unroll
    for (int i = 0; i < 8; i++) {
        float4 o;
        o.x = acc[i][0] + bsum[0];
        o.y = acc[i][1] + bsum[1];
        o.z = acc[i][2] + bsum[2];
        o.w = acc[i][3] + bsum[3];
        *(float4*)(C + (size_t)(m0 + ty * 8 + i) * N + n0 + tx * 4) = o;
    }
}

// ---------------- launch ------------------------------------------------
extern "C" void kernel_launch(void* const* d_in, const int* in_sizes, int n_in,
                              void* d_out, int out_size)
{
    const float* x     = (const float*)d_in[0];  // (T,1,H)
    const float* W_ih  = (const float*)d_in[1];  // (H,H)
    const float* W_hh  = (const float*)d_in[2];  // (H,H)
    const float* b_ih  = (const float*)d_in[3];  // (H)
    const float* b_hh  = (const float*)d_in[4];  // (H)
    const float* W_lin = (const float*)d_in[5];  // (O,H)
    const float* b_lin = (const float*)d_in[6];  // (O)
    const float* h0    = (const float*)d_in[7];  // (1,1,H)
    float* out = (float*)d_out;                  // (T,1,O)

    // Reset g_hs to sentinel (must precede rnn_kernel every launch/replay).
    reset_hs_kernel<<<(T_STEPS * H_DIM / 4) / 256, 256>>>();

    // Phase 1: g_xp = x @ W_ih^T + b_ih + b_hh
    gemm_nt_bias<0><<<dim3(H_DIM / BN, T_STEPS / BM), 256>>>(
        x, W_ih, b_ih, b_hh, nullptr, T_STEPS, H_DIM, H_DIM);

    // Phase 2: sequential recurrence -> g_hs
    rnn_kernel<<<RNN_CTAS, RNN_THREADS>>>(W_hh, h0);

    // Phase 3: out = g_hs @ W_lin^T + b_lin
    gemm_nt_bias<1><<<dim3(O_DIM / BN, T_STEPS / BM), 256>>>(
        nullptr, W_lin, b_lin, nullptr, out, T_STEPS, O_DIM, H_DIM);
}

// round 15
// speedup vs baseline: 1.7887x; 1.0100x over previous
#include <cuda_runtime.h>
#include <math.h>

#define T_STEPS 4096
#define H_DIM   2048
#define O_DIM   512

#define RNN_CTAS    128
#define RNN_THREADS 256

#define SENTINEL 0x7f800001u   // NaN payload; tanh(finite) can never produce it

// ---------------- device scratch (allocation-free rule) ----------------
__device__ float g_xp[(size_t)T_STEPS * H_DIM];   // x @ W_ih^T + b_ih + b_hh
__device__ float g_hs[(size_t)T_STEPS * H_DIM];   // all hidden states h_t

// Morally-strong volatile ops for the data-as-flag protocol (R8, proven).
__device__ __forceinline__ uint4 ld_vol_u4(const uint4* p)
{
    uint4 v;
    asm volatile("ld.volatile.global.v4.u32 {%0,%1,%2,%3}, [%4];"
                 : "=r"(v.x), "=r"(v.y), "=r"(v.z), "=r"(v.w)
                 : "l"(p) : "memory");
    return v;
}
__device__ __forceinline__ void st_vol_f32(float* p, float v)
{
    asm volatile("st.volatile.global.f32 [%0], %1;"
                 :: "l"(p), "f"(v) : "memory");
}
__device__ __forceinline__ bool has_sent(uint4 v)
{
    return (v.x == SENTINEL) | (v.y == SENTINEL) |
           (v.z == SENTINEL) | (v.w == SENTINEL);
}

// ---------------- tf32 helpers -----------------------------------------
__device__ __forceinline__ unsigned f2tf32(float f)
{
    unsigned r;
    asm("cvt.rna.tf32.f32 %0, %1;" : "=r"(r) : "f"(f));
    return r;
}
// split a into hi (tf32) + lo (tf32 of remainder)
__device__ __forceinline__ void tf32_split(float a, unsigned& hi, unsigned& lo)
{
    hi = f2tf32(a);
    lo = f2tf32(a - __uint_as_float(hi));
}
__device__ __forceinline__ void mma_tf32(float4& d,
    unsigned a0, unsigned a1, unsigned a2, unsigned a3,
    unsigned b0, unsigned b1)
{
    asm("mma.sync.aligned.m16n8k8.row.col.f32.tf32.tf32.f32 "
        "{%0,%1,%2,%3}, {%4,%5,%6,%7}, {%8,%9}, {%0,%1,%2,%3};"
        : "+f"(d.x), "+f"(d.y), "+f"(d.z), "+f"(d.w)
        : "r"(a0), "r"(a1), "r"(a2), "r"(a3), "r"(b0), "r"(b1));
}

// ---------------- sentinel reset (graph-replay safe) -------------------
__global__ void reset_hs_kernel()
{
    size_t i = (size_t)blockIdx.x * blockDim.x + threadIdx.x;
    ((uint4*)g_hs)[i] = make_uint4(SENTINEL, SENTINEL, SENTINEL, SENTINEL);
}

// ---------------- persistent recurrence kernel (R14, unchanged) --------
__global__ void __launch_bounds__(RNN_THREADS, 1)
rnn_kernel(const float* __restrict__ W_hh, const float* __restrict__ h0)
{
    __shared__ __align__(16) float hbuf[2][H_DIM];   // double-buffered h
    const int tid  = threadIdx.x;
    const int lane = tid & 31;
    const int wid  = tid >> 5;                    // 0..7
    const int r0   = blockIdx.x * 16 + wid * 2;   // this warp's two rows
    const bool odd = lane & 1;

    float4 w0[16], w1[16];
    const float4* W0 = (const float4*)(W_hh + (size_t)r0 * H_DIM);
    const float4* W1 = (const float4*)(W_hh + (size_t)(r0 + 1) * H_DIM);
#pragma unroll
    for (int j = 0; j < 16; j++) {
        w0[j] = __ldg(&W0[j * 32 + lane]);
        w1[j] = __ldg(&W1[j * 32 + lane]);
    }

    for (int t = 0; t < T_STEPS; t++) {
        const int buf = t & 1;

        float xpv = 0.f;
        if (lane < 2) {
            xpv = __ldg(&g_xp[(size_t)t * H_DIM + r0 + lane]);
        }

        float4 a4, b4;
        if (t == 0) {
            a4 = __ldg(&((const float4*)h0)[tid]);
            b4 = __ldg(&((const float4*)h0)[tid + RNN_THREADS]);
        } else {
            const uint4* hp = (const uint4*)(g_hs + (size_t)(t - 1) * H_DIM);
            uint4 ua, ub;
            bool da = false, db = false;
            do {
                if (!da) { ua = ld_vol_u4(hp + tid);               da = !has_sent(ua); }
                if (!db) { ub = ld_vol_u4(hp + tid + RNN_THREADS); db = !has_sent(ub); }
            } while (!(da && db));
            a4 = make_float4(__uint_as_float(ua.x), __uint_as_float(ua.y),
                             __uint_as_float(ua.z), __uint_as_float(ua.w));
            b4 = make_float4(__uint_as_float(ub.x), __uint_as_float(ub.y),
                             __uint_as_float(ub.z), __uint_as_float(ub.w));
        }

        ((float4*)hbuf[buf])[tid]               = a4;
        ((float4*)hbuf[buf])[tid + RNN_THREADS] = b4;
        __syncthreads();

        float acc0 = 0.f, acc1 = 0.f;
#pragma unroll
        for (int j = 0; j < 16; j++) {
            float4 h4 = ((const float4*)hbuf[buf])[j * 32 + lane];
            acc0 += w0[j].x * h4.x; acc1 += w1[j].x * h4.x;
            acc0 += w0[j].y * h4.y; acc1 += w1[j].y * h4.y;
            acc0 += w0[j].z * h4.z; acc1 += w1[j].z * h4.z;
            acc0 += w0[j].w * h4.w; acc1 += w1[j].w * h4.w;
        }

        // Joint butterfly reduction (5 levels); even lanes -> s0, odd -> s1.
        float mine  = odd ? acc1 : acc0;
        float other = odd ? acc0 : acc1;
        mine += __shfl_xor_sync(0xffffffffu, other, 1);
#pragma unroll
        for (int off = 2; off < 32; off <<= 1) {
            mine += __shfl_xor_sync(0xffffffffu, mine, off);
        }

        if (lane < 2) {
            float v = tanhf(xpv + mine);
            st_vol_f32(&g_hs[(size_t)t * H_DIM + r0 + lane], v);
        }
    }
}

// ---------------- 3xTF32 tensor-core GEMM (phase 0) --------------------
// g_xp[M=T_STEPS, N=H_DIM] = x[M, K=H_DIM] @ W_ih[N, K]^T + b_ih + b_hh
// CTA tile 128x64, BK=16; 8 warps in 4(m) x 2(n); warp tile 32x32
// (2 m16 subtiles x 4 n8 subtiles), mma m16n8k8 with hi/lo tf32 split.
#define TBM 128
#define TBN 64
#define TBK 16
#define TPAD 20   // row stride in floats: float4-aligned, conflict-free frag reads

__global__ void __launch_bounds__(256, 2)
gemm_tf32_phase0(const float* __restrict__ A,      // x: (M, K) row-major
                 const float* __restrict__ B,      // W_ih: (N, K) row-major
                 const float* __restrict__ bias1,
                 const float* __restrict__ bias2,
                 int M, int N, int K)
{
    __shared__ __align__(16) float As2[TBM][TPAD];
    __shared__ __align__(16) float Bs2[TBN][TPAD];

    const int tid    = threadIdx.x;
    const int lane   = tid & 31;
    const int wid    = tid >> 5;
    const int warp_m = wid & 3;          // 0..3 -> m offset warp_m*32
    const int warp_n = wid >> 2;         // 0..1 -> n offset warp_n*32
    const int g      = lane >> 2;        // groupID 0..7
    const int tg     = lane & 3;         // threadID_in_group 0..3
    const int m0     = blockIdx.y * TBM;
    const int n0     = blockIdx.x * TBN;

    float4 acc[2][4];
#pragma unroll
    for (int im = 0; im < 2; im++)
#pragma unroll
        for (int in = 0; in < 4; in++)
            acc[im][in] = make_float4(0.f, 0.f, 0.f, 0.f);

    for (int k0 = 0; k0 < K; k0 += TBK) {
        // A tile: 128x16 = 512 float4, 2 per thread
#pragma unroll
        for (int it = 0; it < 2; it++) {
            int idx = tid + it * 256;
            int row = idx >> 2, kq = idx & 3;
            float4 v = *(const float4*)(A + (size_t)(m0 + row) * K + k0 + kq * 4);
            *(float4*)&As2[row][kq * 4] = v;
        }
        // B tile: 64x16 = 256 float4, 1 per thread
        {
            int row = tid >> 2, kq = tid & 3;
            float4 v = *(const float4*)(B + (size_t)(n0 + row) * K + k0 + kq * 4);
            *(float4*)&Bs2[row][kq * 4] = v;
        }
        __syncthreads();

#pragma unroll
        for (int ks = 0; ks < 2; ks++) {
            const int kb = ks * 8;
            // A fragments for 2 m-subtiles (hi/lo split)
            unsigned ah[2][4], al[2][4];
#pragma unroll
            for (int im = 0; im < 2; im++) {
                const int mb = warp_m * 32 + im * 16;
                tf32_split(As2[mb + g][kb + tg],          ah[im][0], al[im][0]);
                tf32_split(As2[mb + g + 8][kb + tg],      ah[im][1], al[im][1]);
                tf32_split(As2[mb + g][kb + tg + 4],      ah[im][2], al[im][2]);
                tf32_split(As2[mb + g + 8][kb + tg + 4],  ah[im][3], al[im][3]);
            }
            // B fragments for 4 n-subtiles (hi/lo split)
            unsigned bh[4][2], bl[4][2];
#pragma unroll
            for (int in = 0; in < 4; in++) {
                const int nb = warp_n * 32 + in * 8;
                tf32_split(Bs2[nb + g][kb + tg],     bh[in][0], bl[in][0]);
                tf32_split(Bs2[nb + g][kb + tg + 4], bh[in][1], bl[in][1]);
            }
#pragma unroll
            for (int im = 0; im < 2; im++)
#pragma unroll
                for (int in = 0; in < 4; in++) {
                    // lo terms first, then hi*hi
                    mma_tf32(acc[im][in], al[im][0], al[im][1], al[im][2], al[im][3],
                             bh[in][0], bh[in][1]);
                    mma_tf32(acc[im][in], ah[im][0], ah[im][1], ah[im][2], ah[im][3],
                             bl[in][0], bl[in][1]);
                    mma_tf32(acc[im][in], ah[im][0], ah[im][1], ah[im][2], ah[im][3],
                             bh[in][0], bh[in][1]);
                }
        }
        __syncthreads();
    }

    // Epilogue: bias + store. C frag: {x,y} row mb+g cols nb+2tg,2tg+1;
    //                               {z,w} row mb+g+8 same cols.
#pragma unroll
    for (int in = 0; in < 4; in++) {
        const int nb = n0 + warp_n * 32 + in * 8 + 2 * tg;
        float b0 = __ldg(&bias1[nb])     + __ldg(&bias2[nb]);
        float b1 = __ldg(&bias1[nb + 1]) + __ldg(&bias2[nb + 1]);
#pragma unroll
        for (int im = 0; im < 2; im++) {
            const int mb = m0 + warp_m * 32 + im * 16 + g;
            float2 lo = make_float2(acc[im][in].x + b0, acc[im][in].y + b1);
            float2 hi = make_float2(acc[im][in].z + b0, acc[im][in].w + b1);
            *(float2*)(g_xp + (size_t)mb * N + nb)       = lo;
            *(float2*)(g_xp + (size_t)(mb + 8) * N + nb) = hi;
        }
    }
}

// ---------------- tiled fp32 NT GEMM (phase 1 only, R8 scalar) ---------
#define BM 128
#define BN 64
#define BK 16

__global__ void __launch_bounds__(256, 2)
gemm_nt_bias1(const float* __restrict__ B,
              const float* __restrict__ bias1,
              float* __restrict__ C,
              int M, int N, int K)
{
    __shared__ __align__(16) float As[BK][BM + 4];
    __shared__ __align__(16) float Bs[BK][BN + 4];

    const float* A = g_hs;

    const int tid = threadIdx.x;
    const int m0  = blockIdx.y * BM;
    const int n0  = blockIdx.x * BN;
    const int ty  = tid >> 4;
    const int tx  = tid & 15;

    float acc[8][4];
#pragma unroll
    for (int i = 0; i < 8; i++)
#pragma unroll
        for (int j = 0; j < 4; j++) acc[i][j] = 0.f;

    for (int k0 = 0; k0 < K; k0 += BK) {
#pragma unroll
        for (int it = 0; it < 2; it++) {
            int idx = tid + it * 256;
            int row = idx >> 2, kq = idx & 3;
            float4 v = *(const float4*)(A + (size_t)(m0 + row) * K + k0 + kq * 4);
            As[kq * 4 + 0][row] = v.x;
            As[kq * 4 + 1][row] = v.y;
            As[kq * 4 + 2][row] = v.z;
            As[kq * 4 + 3][row] = v.w;
        }
        {
            int row = tid >> 2, kq = tid & 3;
            float4 v = *(const float4*)(B + (size_t)(n0 + row) * K + k0 + kq * 4);
            Bs[kq * 4 + 0][row] = v.x;
            Bs[kq * 4 + 1][row] = v.y;
            Bs[kq * 4 + 2][row] = v.z;
            Bs[kq * 4 + 3][row] = v.w;
        }
        __syncthreads();

#pragma unroll
        for (int kk = 0; kk < BK; kk++) {
            float4 a0 = *(const float4*)&As[kk][ty * 8];
            float4 a1 = *(const float4*)&As[kk][ty * 8 + 4];
            float4 bv = *(const float4*)&Bs[kk][tx * 4];
            float av[8] = {a0.x, a0.y, a0.z, a0.w, a1.x, a1.y, a1.z, a1.w};
            float bb[4] = {bv.x, bv.y, bv.z, bv.w};
#pragma unroll
            for (int i = 0; i < 8; i++)
#pragma unroll
                for (int j = 0; j < 4; j++)
                    acc[i][j] += av[i] * bb[j];
        }
        __syncthreads();
    }

    float bsum[4];
#pragma unroll
    for (int j = 0; j < 4; j++) {
        bsum[j] = __ldg(&bias1[n0 + tx * 4 + j]);
    }
#pragma unroll
    for (int i = 0; i < 8; i++) {
        float4 o;
        o.x = acc[i][0] + bsum[0];
        o.y = acc[i][1] + bsum[1];
        o.z = acc[i][2] + bsum[2];
        o.w = acc[i][3] + bsum[3];
        *(float4*)(C + (size_t)(m0 + ty * 8 + i) * N + n0 + tx * 4) = o;
    }
}

// ---------------- launch ------------------------------------------------
extern "C" void kernel_launch(void* const* d_in, const int* in_sizes, int n_in,
                              void* d_out, int out_size)
{
    const float* x     = (const float*)d_in[0];  // (T,1,H)
    const float* W_ih  = (const float*)d_in[1];  // (H,H)
    const float* W_hh  = (const float*)d_in[2];  // (H,H)
    const float* b_ih  = (const float*)d_in[3];  // (H)
    const float* b_hh  = (const float*)d_in[4];  // (H)
    const float* W_lin = (const float*)d_in[5];  // (O,H)
    const float* b_lin = (const float*)d_in[6];  // (O)
    const float* h0    = (const float*)d_in[7];  // (1,1,H)
    float* out = (float*)d_out;                  // (T,1,O)

    // Reset g_hs to sentinel (must precede rnn_kernel every launch/replay).
    reset_hs_kernel<<<(T_STEPS * H_DIM / 4) / 256, 256>>>();

    // Phase 1: g_xp = x @ W_ih^T + b_ih + b_hh   (3xTF32 tensor cores)
    gemm_tf32_phase0<<<dim3(H_DIM / TBN, T_STEPS / TBM), 256>>>(
        x, W_ih, b_ih, b_hh, T_STEPS, H_DIM, H_DIM);

    // Phase 2: sequential recurrence -> g_hs
    rnn_kernel<<<RNN_CTAS, RNN_THREADS>>>(W_hh, h0);

    // Phase 3: out = g_hs @ W_lin^T + b_lin   (scalar fp32, at floor)
    gemm_nt_bias1<<<dim3(O_DIM / BN, T_STEPS / BM), 256>>>(
        W_lin, b_lin, out, T_STEPS, O_DIM, H_DIM);
}